// round 10
// baseline (speedup 1.0000x reference)
#include <cuda_runtime.h>
#include <cuda_fp16.h>
#include <cstdint>

// Problem constants
#define B_  32
#define T_  4096
#define M_  256     // K dim of GEMM
#define L_  128     // hidden (N dim of GEMM)

#define PAIRS     64            // (b,t) pairs per CTA
#define ROWS      128           // MMA rows: h1 rows 0..63, h2 rows 64..127
#define NTHREADS  256           // 8 warps: 4 pairs x (2 col-half warps)
#define KCHUNK    32            // fp32 elems per k-chunk
#define NCHUNKS   8

#define HSTRIDE   40            // fp16 elems per H tile row (80B; proven conflict-free)
#define VSTRIDE   264           // fp16 elems per V row (528B; proven)

#define HBUF_B    (ROWS * HSTRIDE * 2)       // 10240 B per H buffer

// smem byte offsets
#define SM_H      0                          // 2 x 10240 B (double buffer)
#define SM_V      20480                      // 128 x 264 fp16 = 67584 B
#define SM_WS     88064                      // 128 floats
#define SM_SCORE  88576                      // 2 x 128 floats (per column-half)
#define SMEM_BYTES 89600

#define BAR_SYNC(id, cnt) asm volatile("bar.sync %0, %1;" :: "r"(id), "r"(cnt) : "memory")

__device__ __half g_Vh[L_ * M_];

__device__ __forceinline__ float fast_tanh(float x) {
    float e = __expf(2.0f * x);
    return 1.0f - __fdividef(2.0f, e + 1.0f);
}

__device__ __forceinline__ uint32_t pack2h(float a, float b) {
    __half2 hv; hv.x = __float2half_rn(a); hv.y = __float2half_rn(b);
    return *reinterpret_cast<uint32_t*>(&hv);
}

__device__ __forceinline__ void mma_f16(float* c, const uint32_t* a,
                                        uint32_t b0, uint32_t b1) {
    asm("mma.sync.aligned.m16n8k16.row.col.f32.f16.f16.f32 "
        "{%0,%1,%2,%3}, {%4,%5,%6,%7}, {%8,%9}, {%0,%1,%2,%3};\n"
        : "+f"(c[0]), "+f"(c[1]), "+f"(c[2]), "+f"(c[3])
        : "r"(a[0]), "r"(a[1]), "r"(a[2]), "r"(a[3]), "r"(b0), "r"(b1));
}

__device__ __forceinline__ void ldsm4(uint32_t& r0, uint32_t& r1, uint32_t& r2, uint32_t& r3,
                                      uint32_t addr) {
    asm volatile("ldmatrix.sync.aligned.m8n8.x4.shared.b16 {%0,%1,%2,%3}, [%4];\n"
                 : "=r"(r0), "=r"(r1), "=r"(r2), "=r"(r3) : "r"(addr));
}

// ---------------- kernel 1: round V to fp16 ----------------
__global__ void vprep_kernel(const float* __restrict__ v_tp) {
    int i = blockIdx.x * blockDim.x + threadIdx.x;
    if (i < L_ * M_) g_Vh[i] = __float2half_rn(v_tp[i]);
}

// ---------------- kernel 2: main ----------------
extern __shared__ char smem[];

__global__ void __launch_bounds__(NTHREADS, 2)
topo_attn_kernel(const float* __restrict__ h1, const float* __restrict__ h2,
                 const float* __restrict__ w_tp, float* __restrict__ out)
{
    uint32_t sb;
    asm("{ .reg .u64 t; cvta.to.shared.u64 t, %1; cvt.u32.u64 %0, t; }"
        : "=r"(sb) : "l"(smem));

    const int tid  = threadIdx.x;
    const int warp = tid >> 5;
    const int lane = tid & 31;
    const int pair0 = blockIdx.x * PAIRS;

    float* ws     = reinterpret_cast<float*>(smem + SM_WS);
    float* scoreA = reinterpret_cast<float*>(smem + SM_SCORE);          // col half 0
    float* scoreB = scoreA + 128;                                       // col half 1
    __half* Vs    = reinterpret_cast<__half*>(smem + SM_V);

    // warp tiling: 4 row-group pairs x 2 col-halves
    const int wpair = warp >> 1;       // 0..3 -> rows wpair*32 .. +31 (produced by this pair)
    const int wc    = warp & 1;        // 0..1 -> cols wc*64 .. +63
    const int rb    = wpair * 32;
    const int cb    = wc * 64;

    // pair-local H staging coords: 64 threads stage 32 rows x 32 fp32 per chunk
    const int local = tid & 63;                    // within pair
    const int hc4   = local & 7;                   // 8 lanes per row -> 4 lines per LDG.128
    const float* hsrc[4];
    int hrow[4];
    #pragma unroll
    for (int i = 0; i < 4; ++i) {
        int R = rb + (local >> 3) + 8 * i;         // CTA row
        hrow[i] = R;
        hsrc[i] = (R < PAIRS)
            ? (h1 + (size_t)(pair0 + R) * M_)
            : (h2 + (size_t)(pair0 + R - PAIRS) * M_);
    }

    // ---- issue chunk-0 LDGs immediately
    float4 f[4];
    #pragma unroll
    for (int i = 0; i < 4; ++i)
        f[i] = *reinterpret_cast<const float4*>(hsrc[i] + hc4 * 4);

    // ---- while they fly: copy V (fp16, L2-resident) and w into smem
    if (tid < L_) ws[tid] = w_tp[tid];
    #pragma unroll
    for (int i = 0; i < 16; ++i) {
        int idx = i * NTHREADS + tid;      // uint4 idx over 128*32
        int r   = idx >> 5;
        int c8  = idx & 31;
        uint4 v = *reinterpret_cast<const uint4*>(g_Vh + r * M_ + c8 * 8);
        *reinterpret_cast<uint4*>(Vs + r * VSTRIDE + c8 * 8) = v;
    }
    __syncthreads();   // V + ws visible; after this, pairs run independently

    // ldmatrix lane-address decomposition (within a 16-row / 16-col tile)
    const int arow = (lane & 7) + ((lane >> 3) & 1) * 8;
    const int acol = (lane >> 4) * 8;
    const int brow = (lane & 7) + ((lane >> 4) & 1) * 8;
    const int bcol = ((lane >> 3) & 1) * 8;

    const uint32_t a_h0 = sb + SM_H + ((rb + arow) * HSTRIDE + acol) * 2;
    const uint32_t b_v0 = sb + SM_V + ((cb + brow) * VSTRIDE + bcol) * 2;

    float acc[2][8][4];                // [row-tile m16][col-tile n8][frag]
    #pragma unroll
    for (int rt = 0; rt < 2; ++rt)
        #pragma unroll
        for (int n = 0; n < 8; ++n)
            #pragma unroll
            for (int q = 0; q < 4; ++q) acc[rt][n][q] = 0.0f;

    const int barid = 1 + wpair;       // named barriers 1..4, 64 threads each

    for (int kc = 0; kc < NCHUNKS; ++kc) {
        const int buf = kc & 1;

        // ---- cvt + store chunk kc into buf (pair-local rows only)
        __half* Hs = reinterpret_cast<__half*>(smem + SM_H + buf * HBUF_B);
        #pragma unroll
        for (int i = 0; i < 4; ++i) {
            uint2 hv;
            hv.x = pack2h(f[i].x, f[i].y);
            hv.y = pack2h(f[i].z, f[i].w);
            *reinterpret_cast<uint2*>(Hs + hrow[i] * HSTRIDE + hc4 * 4) = hv;
        }

        // ---- issue next chunk's LDGs before the barrier (latency overlaps wait)
        if (kc + 1 < NCHUNKS) {
            #pragma unroll
            for (int i = 0; i < 4; ++i)
                f[i] = *reinterpret_cast<const float4*>(hsrc[i] + (kc + 1) * KCHUNK + hc4 * 4);
        }

        BAR_SYNC(barid, 64);   // pair-scoped: buf ready; proves pair past mma(kc-2)

        // ---- mma over this chunk: 2 ksteps of k16
        const uint32_t a_hb = a_h0 + buf * HBUF_B;
        #pragma unroll
        for (int ks = 0; ks < 2; ++ks) {
            const int kk = ks * 16;
            uint32_t a0[4], a1[4];
            ldsm4(a0[0], a0[1], a0[2], a0[3], a_hb + kk * 2);
            ldsm4(a1[0], a1[1], a1[2], a1[3], a_hb + kk * 2 + 16 * HSTRIDE * 2);
            const uint32_t kb = (kc * KCHUNK + kk) * 2;
            #pragma unroll
            for (int p = 0; p < 4; ++p) {
                uint32_t b0, b1, b2, b3;
                ldsm4(b0, b1, b2, b3, b_v0 + p * (16 * VSTRIDE * 2) + kb);
                mma_f16(acc[0][2 * p],     a0, b0, b1);
                mma_f16(acc[0][2 * p + 1], a0, b2, b3);
                mma_f16(acc[1][2 * p],     a1, b0, b1);
                mma_f16(acc[1][2 * p + 1], a1, b2, b3);
            }
        }
    }

    // ---- epilogue: partial score over this warp's 64 columns
    {
        const int g = lane >> 2;
        const int t = lane & 3;
        float p0[2], p1[2];             // [row-tile] rows g / g+8
        #pragma unroll
        for (int rt = 0; rt < 2; ++rt) { p0[rt] = 0.f; p1[rt] = 0.f; }
        #pragma unroll
        for (int nt = 0; nt < 8; ++nt) {
            float w0 = ws[cb + nt * 8 + 2 * t];
            float w1 = ws[cb + nt * 8 + 2 * t + 1];
            #pragma unroll
            for (int rt = 0; rt < 2; ++rt) {
                p0[rt] += w0 * fast_tanh(acc[rt][nt][0]) + w1 * fast_tanh(acc[rt][nt][1]);
                p1[rt] += w0 * fast_tanh(acc[rt][nt][2]) + w1 * fast_tanh(acc[rt][nt][3]);
            }
        }
        #pragma unroll
        for (int off = 1; off < 4; off <<= 1) {
            #pragma unroll
            for (int rt = 0; rt < 2; ++rt) {
                p0[rt] += __shfl_xor_sync(0xffffffffu, p0[rt], off);
                p1[rt] += __shfl_xor_sync(0xffffffffu, p1[rt], off);
            }
        }
        if (t == 0) {
            float* sc = wc ? scoreB : scoreA;
            #pragma unroll
            for (int rt = 0; rt < 2; ++rt) {
                sc[rb + rt * 16 + g]     = p0[rt];
                sc[rb + rt * 16 + g + 8] = p1[rt];
            }
        }
    }
    __syncthreads();   // re-converge all pairs

    // ---- 2-way softmax + store. out shape (B, 2, T)
    if (tid < PAIRS) {
        float s1 = scoreA[tid]         + scoreB[tid];
        float s2 = scoreA[PAIRS + tid] + scoreB[PAIRS + tid];
        float d  = s2 - s1;
        float a1 = 1.0f / (1.0f + __expf(d));
        float a2 = 1.0f / (1.0f + __expf(-d));
        int gp = pair0 + tid;
        int b  = gp >> 12;          // / T_
        int tt = gp & (T_ - 1);
        out[(size_t)b * (2 * T_) + tt]      = a1;
        out[(size_t)b * (2 * T_) + T_ + tt] = a2;
    }
}

extern "C" void kernel_launch(void* const* d_in, const int* in_sizes, int n_in,
                              void* d_out, int out_size) {
    const float* h1   = (const float*)d_in[0];
    const float* h2   = (const float*)d_in[1];
    const float* w_tp = (const float*)d_in[2];
    const float* v_tp = (const float*)d_in[3];
    float* out = (float*)d_out;

    cudaFuncSetAttribute(topo_attn_kernel,
                         cudaFuncAttributeMaxDynamicSharedMemorySize, SMEM_BYTES);

    vprep_kernel<<<(L_ * M_ + 255) / 256, 256>>>(v_tp);

    int grid = (B_ * T_) / PAIRS;   // 2048
    topo_attn_kernel<<<grid, NTHREADS, SMEM_BYTES>>>(h1, h2, w_tp, out);
}